// round 8
// baseline (speedup 1.0000x reference)
#include <cuda_runtime.h>
#include <cuda_bf16.h>

// Problem constants
#define BATCH   4
#define LENGTH  512
#define DMODEL  128
#define DINNER  256
#define DSTATE  256
#define MROWS   (BATCH * LENGTH)        // 2048
#define LOG2E   1.4426950408889634f
#define NC      16                      // scan chunks
#define TC      32                      // steps per chunk (NC*TC == LENGTH)

typedef unsigned long long ull;

// Scratch (allocation-free: __device__ globals)
__device__ float g_xs[MROWS * DINNER];     // xs (first half of in_proj)
__device__ float g_sz[MROWS * DINNER];     // silu(z)
__device__ float g_delta[MROWS * DINNER];  // xs @ W_delta
__device__ float g_bu[MROWS * DSTATE];     // (xs @ W_B) * xs   (elementwise)
__device__ float g_Cv[MROWS * DINNER];     // xs @ W_C
__device__ float g_y[MROWS * DINNER];      // scan output * silu(z)

// Chunked-scan intermediates: layout [((b*NC + c)*256 + d)*256 + n]
__device__ float g_P  [BATCH * NC * DINNER * DSTATE];  // per-chunk prod of a_t
__device__ float g_Sf [BATCH * NC * DINNER * DSTATE];  // per-chunk local final state

// ---- packed f32x2 helpers (Blackwell FFMA2 path; .rn = bit-identical) ----
__device__ __forceinline__ ull pk2(float lo, float hi) {
    ull r; asm("mov.b64 %0, {%1, %2};" : "=l"(r) : "f"(lo), "f"(hi)); return r;
}
__device__ __forceinline__ float2 upk2(ull v) {
    float2 r; asm("mov.b64 {%0, %1}, %2;" : "=f"(r.x), "=f"(r.y) : "l"(v)); return r;
}
__device__ __forceinline__ ull mul2_(ull a, ull b) {
    ull d; asm("mul.rn.f32x2 %0, %1, %2;" : "=l"(d) : "l"(a), "l"(b)); return d;
}
__device__ __forceinline__ ull fma2_(ull a, ull b, ull c) {
    ull d; asm("fma.rn.f32x2 %0, %1, %2, %3;" : "=l"(d) : "l"(a), "l"(b), "l"(c)); return d;
}
__device__ __forceinline__ float ex2f(float x) {
    float e; asm("ex2.approx.ftz.f32 %0, %1;" : "=f"(e) : "f"(x)); return e;
}

// ---------------------------------------------------------------------------
// Tiled fp32 GEMM: C tile 32x64 per block, 128 threads, thread tile 4x4.
// ---------------------------------------------------------------------------
template <int MODE>
__global__ __launch_bounds__(128)
void gemm_kernel(const float* __restrict__ Ag_,
                 const float* __restrict__ B0,
                 const float* __restrict__ B1,
                 const float* __restrict__ B2,
                 float* __restrict__ Og)
{
    constexpr int K   = (MODE == 0) ? 128 : 256;
    constexpr int LDB = (MODE == 0) ? 512 : ((MODE == 1) ? 256 : 128);

    __shared__ float As[16][36];
    __shared__ float Bs[16][68];

    const int tid = threadIdx.x;
    const int tx  = tid & 15;
    const int ty  = tid >> 4;
    const int m0  = blockIdx.y * 32;

    const float* Ag;
    const float* Bg;
    int n0;
    int which = 0;
    if (MODE == 1) {
        which = blockIdx.x >> 2;              // 0: W_delta, 1: W_B, 2: W_C
        n0 = (blockIdx.x & 3) * 64;
        Bg = (which == 0) ? B0 : ((which == 1) ? B1 : B2);
        Ag = g_xs;
    } else {
        n0 = blockIdx.x * 64;
        Bg = B0;
        Ag = (MODE == 0) ? Ag_ : g_y;
    }

    const int aRow  = tid >> 2;
    const int aC4   = (tid & 3) << 2;
    const int bRowk = tid >> 4;
    const int bC4   = (tid & 15) << 2;

    float4 aR;
    float4 bR[2];
    aR = *(const float4*)(Ag + (size_t)(m0 + aRow) * K + aC4);
#pragma unroll
    for (int r = 0; r < 2; r++)
        bR[r] = *(const float4*)(Bg + (size_t)(bRowk + r * 8) * LDB + n0 + bC4);

    float acc[4][4];
#pragma unroll
    for (int i = 0; i < 4; i++)
#pragma unroll
        for (int j = 0; j < 4; j++) acc[i][j] = 0.f;

    for (int k0 = 0; k0 < K; k0 += 16) {
        As[aC4 + 0][aRow] = aR.x;
        As[aC4 + 1][aRow] = aR.y;
        As[aC4 + 2][aRow] = aR.z;
        As[aC4 + 3][aRow] = aR.w;
#pragma unroll
        for (int r = 0; r < 2; r++)
            *(float4*)&Bs[bRowk + r * 8][bC4] = bR[r];
        __syncthreads();

        if (k0 + 16 < K) {
            aR = *(const float4*)(Ag + (size_t)(m0 + aRow) * K + (k0 + 16) + aC4);
#pragma unroll
            for (int r = 0; r < 2; r++)
                bR[r] = *(const float4*)(Bg + (size_t)(k0 + 16 + bRowk + r * 8) * LDB + n0 + bC4);
        }

#pragma unroll
        for (int kk = 0; kk < 16; kk++) {
            float4 av = *(const float4*)&As[kk][ty * 4];
            float4 bv = *(const float4*)&Bs[kk][tx * 4];
            float a[4] = {av.x, av.y, av.z, av.w};
            float b[4] = {bv.x, bv.y, bv.z, bv.w};
#pragma unroll
            for (int i = 0; i < 4; i++)
#pragma unroll
                for (int j = 0; j < 4; j++)
                    acc[i][j] = fmaf(a[i], b[j], acc[i][j]);
        }
        __syncthreads();
    }

#pragma unroll
    for (int i = 0; i < 4; i++) {
        int m = m0 + ty * 4 + i;
#pragma unroll
        for (int j = 0; j < 4; j++) {
            int c = n0 + tx * 4 + j;
            float v = acc[i][j];
            if (MODE == 0) {
                if (c < 256) {
                    g_xs[m * 256 + c] = v;
                } else {
                    float sig = 1.f / (1.f + __expf(-v));
                    g_sz[m * 256 + (c - 256)] = v * sig;   // silu(z)
                }
            } else if (MODE == 1) {
                if (which == 0)      g_delta[m * 256 + c] = v;
                else if (which == 1) g_bu[m * 256 + c] = v * g_xs[m * 256 + c];
                else                 g_Cv[m * 256 + c] = v;
            } else {
                Og[m * 128 + c] = v;
            }
        }
    }
}

// ---------------------------------------------------------------------------
// Scan pass 1: chunks 0..NC-2. Each WARP handles 2 consecutive d's.
// f32x2-packed state update; next-step operands software-prefetched.
//   Sf = local final state (zero-init recurrence)
//   P  = exp2(Ae * sum_chunk delta)
// ---------------------------------------------------------------------------
__global__ __launch_bounds__(128, 6)
void scan_p1(const float* __restrict__ A)
{
    const int warp = threadIdx.x >> 5;
    const int lane = threadIdx.x & 31;
    int bid = blockIdx.x;                  // ((c*BATCH + b)*32 + dblk)
    const int dblk = bid & 31;  bid >>= 5;
    const int b    = bid & 3;   bid >>= 2;
    const int c    = bid;                  // 0 .. NC-2
    const int d0   = (dblk * 4 + warp) * 2;
    const int nb   = lane << 3;

    ull Ae2[2][4];
#pragma unroll
    for (int di = 0; di < 2; di++)
#pragma unroll
        for (int k = 0; k < 4; k++)
            Ae2[di][k] = pk2(A[(d0 + di) * 256 + nb + 2 * k]     * LOG2E,
                             A[(d0 + di) * 256 + nb + 2 * k + 1] * LOG2E);

    const int base = b * LENGTH * 256;
    const float* __restrict__ bu = g_bu    + base;
    const float* __restrict__ dp = g_delta + base;

    ull s2[2][4];
#pragma unroll
    for (int di = 0; di < 2; di++)
#pragma unroll
        for (int k = 0; k < 4; k++) s2[di][k] = 0ull;
    float dsum[2] = {0.f, 0.f};

    const int t0 = c * TC, t1 = t0 + TC;
    ulonglong2 buA = *(const ulonglong2*)(bu + t0 * 256 + nb);
    ulonglong2 buB = *(const ulonglong2*)(bu + t0 * 256 + nb + 4);
    float2 dc = *(const float2*)(dp + t0 * 256 + d0);

    for (int t = t0; t < t1; t++) {
        const int tn = (t + 1 < t1) ? t + 1 : t;
        ulonglong2 buA_n = *(const ulonglong2*)(bu + tn * 256 + nb);
        ulonglong2 buB_n = *(const ulonglong2*)(bu + tn * 256 + nb + 4);
        float2 dn = *(const float2*)(dp + tn * 256 + d0);

        ull bu2[4] = {buA.x, buA.y, buB.x, buB.y};
        float del[2] = {dc.x, dc.y};
#pragma unroll
        for (int di = 0; di < 2; di++) {
            dsum[di] += del[di];
            ull del2 = pk2(del[di], del[di]);
#pragma unroll
            for (int k = 0; k < 4; k++) {
                float2 pf = upk2(mul2_(del2, Ae2[di][k]));
                ull e2v = pk2(ex2f(pf.x), ex2f(pf.y));
                ull dbu = mul2_(del2, bu2[k]);
                s2[di][k] = fma2_(e2v, s2[di][k], dbu);
            }
        }
        buA = buA_n; buB = buB_n; dc = dn;
    }

#pragma unroll
    for (int di = 0; di < 2; di++) {
        float P[8];
#pragma unroll
        for (int k = 0; k < 4; k++) {
            float2 ae = upk2(Ae2[di][k]);
            P[2 * k]     = ex2f(dsum[di] * ae.x);
            P[2 * k + 1] = ex2f(dsum[di] * ae.y);
        }
        const size_t o = ((size_t)((b * NC + c) * 256 + d0 + di)) * 256 + nb;
        *(float4*)(g_P + o)     = *(float4*)&P[0];
        *(float4*)(g_P + o + 4) = *(float4*)&P[4];
        *(ulonglong2*)(g_Sf + o)     = make_ulonglong2(s2[di][0], s2[di][1]);
        *(ulonglong2*)(g_Sf + o + 4) = make_ulonglong2(s2[di][2], s2[di][3]);
    }
}

// ---------------------------------------------------------------------------
// Scan pass 2 (fused chunk-summary): each WARP handles 2 consecutive d's.
// Prologue reconstructs both initial states from preceding chunks' (P, Sf).
// Main loop: f32x2-packed update + y-dot, prefetched operands, 6-shfl
// reduction; lane 0 / lane 16 store y*silu(z) for d0 / d0+1 directly.
// ---------------------------------------------------------------------------
__global__ __launch_bounds__(128, 5)
void scan_p2(const float* __restrict__ A)
{
    const int warp = threadIdx.x >> 5;
    const int lane = threadIdx.x & 31;
    int bid = blockIdx.x;                  // ((c*BATCH + b)*32 + dblk)
    const int dblk = bid & 31;  bid >>= 5;
    const int b    = bid & 3;   bid >>= 2;
    const int c    = bid;                  // 0 .. NC-1
    const int d0   = (dblk * 4 + warp) * 2;
    const int nb   = lane << 3;

    ull Ae2[2][4];
#pragma unroll
    for (int di = 0; di < 2; di++)
#pragma unroll
        for (int k = 0; k < 4; k++)
            Ae2[di][k] = pk2(A[(d0 + di) * 256 + nb + 2 * k]     * LOG2E,
                             A[(d0 + di) * 256 + nb + 2 * k + 1] * LOG2E);

    // Reconstruct initial states from chunks 0..c-1 (scalar; runs once)
    float s[2][8];
#pragma unroll
    for (int di = 0; di < 2; di++)
#pragma unroll
        for (int j = 0; j < 8; j++) s[di][j] = 0.f;
    for (int cc = 0; cc < c; cc++) {
#pragma unroll
        for (int di = 0; di < 2; di++) {
            const size_t o = ((size_t)((b * NC + cc) * 256 + d0 + di)) * 256 + nb;
            float P[8], Sf[8];
            *(float4*)&P[0]  = *(const float4*)(g_P  + o);
            *(float4*)&P[4]  = *(const float4*)(g_P  + o + 4);
            *(float4*)&Sf[0] = *(const float4*)(g_Sf + o);
            *(float4*)&Sf[4] = *(const float4*)(g_Sf + o + 4);
#pragma unroll
            for (int j = 0; j < 8; j++)
                s[di][j] = fmaf(P[j], s[di][j], Sf[j]);
        }
    }
    ull s2[2][4];
#pragma unroll
    for (int di = 0; di < 2; di++)
#pragma unroll
        for (int k = 0; k < 4; k++)
            s2[di][k] = pk2(s[di][2 * k], s[di][2 * k + 1]);

    const int base = b * LENGTH * 256;
    const float* __restrict__ bu  = g_bu    + base;
    const float* __restrict__ Cp  = g_Cv    + base;
    const float* __restrict__ dp  = g_delta + base;
    const float* __restrict__ szp = g_sz    + base;
    float*       __restrict__ yp  = g_y     + base;

    const int t0 = c * TC, t1 = t0 + TC;
    ulonglong2 buA = *(const ulonglong2*)(bu + t0 * 256 + nb);
    ulonglong2 buB = *(const ulonglong2*)(bu + t0 * 256 + nb + 4);
    ulonglong2 cvA = *(const ulonglong2*)(Cp + t0 * 256 + nb);
    ulonglong2 cvB = *(const ulonglong2*)(Cp + t0 * 256 + nb + 4);
    float2 dc = *(const float2*)(dp + t0 * 256 + d0);

    for (int t = t0; t < t1; t++) {
        const int tn = (t + 1 < t1) ? t + 1 : t;
        ulonglong2 buA_n = *(const ulonglong2*)(bu + tn * 256 + nb);
        ulonglong2 buB_n = *(const ulonglong2*)(bu + tn * 256 + nb + 4);
        ulonglong2 cvA_n = *(const ulonglong2*)(Cp + tn * 256 + nb);
        ulonglong2 cvB_n = *(const ulonglong2*)(Cp + tn * 256 + nb + 4);
        float2 dn = *(const float2*)(dp + tn * 256 + d0);

        ull bu2[4] = {buA.x, buA.y, buB.x, buB.y};
        ull cv2[4] = {cvA.x, cvA.y, cvB.x, cvB.y};
        float del[2] = {dc.x, dc.y};
        float y[2];
#pragma unroll
        for (int di = 0; di < 2; di++) {
            ull del2 = pk2(del[di], del[di]);
            ull ypk = 0ull;
#pragma unroll
            for (int k = 0; k < 4; k++) {
                float2 pf = upk2(mul2_(del2, Ae2[di][k]));
                ull e2v = pk2(ex2f(pf.x), ex2f(pf.y));
                ull dbu = mul2_(del2, bu2[k]);
                s2[di][k] = fma2_(e2v, s2[di][k], dbu);
                ypk = (k == 0) ? mul2_(s2[di][k], cv2[k])
                               : fma2_(s2[di][k], cv2[k], ypk);
            }
            float2 yf = upk2(ypk);
            y[di] = yf.x + yf.y;
        }

        // 6-shfl reduction: xor16 both, select halves, xor8/4/2/1
        y[0] += __shfl_xor_sync(0xffffffffu, y[0], 16);
        y[1] += __shfl_xor_sync(0xffffffffu, y[1], 16);
        float v = (lane < 16) ? y[0] : y[1];
        v += __shfl_xor_sync(0xffffffffu, v, 8);
        v += __shfl_xor_sync(0xffffffffu, v, 4);
        v += __shfl_xor_sync(0xffffffffu, v, 2);
        v += __shfl_xor_sync(0xffffffffu, v, 1);
        // lane 0 holds y[d0], lane 16 holds y[d0+1] — store directly
        if (lane == 0)
            yp[t * 256 + d0]     = v * szp[t * 256 + d0];
        if (lane == 16)
            yp[t * 256 + d0 + 1] = v * szp[t * 256 + d0 + 1];

        buA = buA_n; buB = buB_n; cvA = cvA_n; cvB = cvB_n; dc = dn;
    }
}

// ---------------------------------------------------------------------------
// Inputs (metadata order): x, W_in, W_delta, W_B, W_C, W_out, A, D(unused)
// ---------------------------------------------------------------------------
extern "C" void kernel_launch(void* const* d_in, const int* in_sizes, int n_in,
                              void* d_out, int out_size)
{
    const float* x       = (const float*)d_in[0];
    const float* W_in    = (const float*)d_in[1];
    const float* W_delta = (const float*)d_in[2];
    const float* W_B     = (const float*)d_in[3];
    const float* W_C     = (const float*)d_in[4];
    const float* W_out   = (const float*)d_in[5];
    const float* A       = (const float*)d_in[6];
    float* out = (float*)d_out;

    // 1) in_proj + split + silu(z)
    gemm_kernel<0><<<dim3(8, 64), 128>>>(x, W_in, nullptr, nullptr, nullptr);
    // 2) delta / bu / Cv projections (fused triple GEMM)
    gemm_kernel<1><<<dim3(12, 64), 128>>>(nullptr, W_delta, W_B, W_C, nullptr);
    // 3) chunked selective scan
    scan_p1<<<(NC - 1) * BATCH * 32, 128>>>(A);
    scan_p2<<<NC * BATCH * 32, 128>>>(A);
    // 4) out_proj
    gemm_kernel<2><<<dim3(2, 64), 128>>>(nullptr, W_out, nullptr, nullptr, out);
}